// round 11
// baseline (speedup 1.0000x reference)
#include <cuda_runtime.h>
#include <cstdint>
#include <math.h>

#define T_LEN 2048
#define BSZ   32
#define DIM   256
#define HID   256
#define LAY   2

typedef unsigned long long ull;

// Scratch: gx[t][l][gate3][b][h]  (2048*2*3*32*256 floats = 402MB)
__device__ float g_gx[(size_t)T_LEN * LAY * 3 * BSZ * HID];

__device__ __forceinline__ void ffma2(ull& d, ull a, ull b) {
    asm("fma.rn.f32x2 %0, %1, %2, %0;" : "+l"(d) : "l"(a), "l"(b));
}
__device__ __forceinline__ float2 unpack2(ull v) {
    float2 r; asm("mov.b64 {%0, %1}, %2;" : "=f"(r.x), "=f"(r.y) : "l"(v)); return r;
}
__device__ __forceinline__ float hsum2(ull v) {
    float2 r = unpack2(v); return r.x + r.y;
}
__device__ __forceinline__ void cp_async16(uint32_t sdst, const void* gsrc) {
    asm volatile("cp.async.ca.shared.global [%0], [%1], 16;" :: "r"(sdst), "l"(gsrc));
}

// ---------------------------------------------------------------------------
// Kernel 1: gx GEMM. 128m x 128n CTA tile, 8x8 thread tile, K chunks of 64,
// cp.async double-buffered. (unchanged — measured ~1.21 ms)
// ---------------------------------------------------------------------------
#define GPAD 68
#define STG_F (128 * GPAD)

__global__ __launch_bounds__(256, 1)
void gx_gemm_kernel(const float* __restrict__ x, const float* __restrict__ Wx,
                    const float* __restrict__ bx)
{
    extern __shared__ float sm1[];
    float* sA = sm1;                 // [2][128][GPAD]
    float* sB = sm1 + 2 * STG_F;     // [2][128][GPAD]

    const int tid = threadIdx.x;
    const int tx  = tid & 15;
    const int ty  = tid >> 4;
    const int nbase = blockIdx.x * 128;
    const int mbase = blockIdx.y * 128;

    const uint32_t sA_u = (uint32_t)__cvta_generic_to_shared(sA);
    const uint32_t sB_u = (uint32_t)__cvta_generic_to_shared(sB);

    auto issue = [&](int stage, int kofs) {
        for (int idx = tid; idx < 128 * 16; idx += 256) {
            int r = idx >> 4, q = idx & 15;
            uint32_t off = (uint32_t)((stage * STG_F + r * GPAD + (q << 2)) * 4);
            cp_async16(sA_u + off, x  + (((size_t)(mbase + r)) << 8) + kofs + (q << 2));
            cp_async16(sB_u + off, Wx + (((size_t)(nbase + r)) << 8) + kofs + (q << 2));
        }
        asm volatile("cp.async.commit_group;");
    };

    int   ncol[8];
    float bias[8];
#pragma unroll
    for (int jj = 0; jj < 8; jj++) {
        ncol[jj] = nbase + tx + 16 * jj;
        bias[jj] = bx[ncol[jj]];
    }

    ull acc2[8][8];
#pragma unroll
    for (int i = 0; i < 8; i++)
#pragma unroll
        for (int j = 0; j < 8; j++) acc2[i][j] = 0ull;

    issue(0, 0);

    for (int kc = 0; kc < 4; kc++) {
        if (kc < 3) {
            issue((kc + 1) & 1, (kc + 1) * 64);
            asm volatile("cp.async.wait_group 1;");
        } else {
            asm volatile("cp.async.wait_group 0;");
        }
        __syncthreads();

        const float* cA = sA + (kc & 1) * STG_F;
        const float* cB = sB + (kc & 1) * STG_F;
#pragma unroll 2
        for (int q = 0; q < 16; q++) {
            ulonglong2 av[8], bv[8];
#pragma unroll
            for (int i = 0; i < 8; i++)
                av[i] = *reinterpret_cast<const ulonglong2*>(cA + (ty * 8 + i) * GPAD + (q << 2));
#pragma unroll
            for (int j = 0; j < 8; j++)
                bv[j] = *reinterpret_cast<const ulonglong2*>(cB + (tx + 16 * j) * GPAD + (q << 2));
#pragma unroll
            for (int i = 0; i < 8; i++)
#pragma unroll
                for (int j = 0; j < 8; j++) {
                    ffma2(acc2[i][j], av[i].x, bv[j].x);
                    ffma2(acc2[i][j], av[i].y, bv[j].y);
                }
        }
        __syncthreads();
    }

#pragma unroll
    for (int jj = 0; jj < 8; jj++) {
        const int n  = ncol[jj];
        const int l  = n / 768;
        const int rr = n - l * 768;
        const int g3 = rr >> 8;
        const int h  = rr & 255;
#pragma unroll
        for (int ii = 0; ii < 8; ii++) {
            const int m = mbase + ty * 8 + ii;
            const int b = m >> 11;
            const int t = m & 2047;
            const size_t o =
                ((((size_t)t * LAY + l) * 3 + g3) * BSZ + b) * HID + h;
            g_gx[o] = hsum2(acc2[ii][jj]) + bias[jj];
        }
    }
}

// ---------------------------------------------------------------------------
// Kernel 2: 8-CTA-cluster persistent GRU scan, 2 CTAs/SM (latency hiding).
// 256 CTAs = 4 groups x 8 batch-chunks(4) x 8-CTA cluster, 128 threads each.
// CTA owns 32 h-outputs: gates r,z rows in regs (k-pair packed), gate-n row
// in smem float2 plane sw3[kpair][lane] (LDS.64 = pre-packed, conflict-free).
// Single-phase combine: thread (h,b) reduces 12 scalar partials, computes
// r/z/n/h, 8 pre-mapa'd remote scalar stores. One __syncthreads per step.
// ---------------------------------------------------------------------------
#define SC_THREADS 128
#define SW3_U   (128 * 32)           // ull entries (float2 k-pairs)
#define PART_F  (4 * 4 * 96)         // [b][kc][row]
#define HBUF_F  (2 * 4 * 256)        // [p][b][k]

__device__ __forceinline__ void cluster_arrive()
{ asm volatile("barrier.cluster.arrive.aligned;" ::: "memory"); }
__device__ __forceinline__ void cluster_wait()
{ asm volatile("barrier.cluster.wait.aligned;" ::: "memory"); }
__device__ __forceinline__ float sig_fast(float x) {
    return __fdividef(1.f, 1.f + __expf(-x));
}
__device__ __forceinline__ float tanh_fast(float x) {
    x = fminf(fmaxf(x, -15.f), 15.f);
    float e = __expf(2.f * x);
    return __fdividef(e - 1.f, e + 1.f);
}

__global__ void __cluster_dims__(8, 1, 1) __launch_bounds__(SC_THREADS, 2)
gru_scan_kernel(const float* __restrict__ Wh, const float* __restrict__ bh,
                float* __restrict__ out)
{
    extern __shared__ float sm[];
    ull*   sw3  = reinterpret_cast<ull*>(sm);    // [128 kpair][32 lane]
    float* part = sm + 2 * SW3_U;                // [4 b][4 kc][96 row]
    float* hbuf = part + PART_F;                 // [2 p][4 b][256 k]

    const int tid  = threadIdx.x;
    const int lane = tid & 31;
    const int kc   = tid >> 5;          // warp id = k-chunk = combine batch
    const int k0   = kc << 6;

    const int rank = blockIdx.x & 7;
    const int cid  = blockIdx.x >> 3;   // 0..31
    const int g    = cid >> 3;          // group
    const int c    = cid & 7;           // batch chunk
    const int l    = g >> 1;
    const int dir  = g & 1;
    const int b0   = c * 4;

    const int hout = rank * 32 + lane;  // owned h-index (dot rows & combine)
    const int bb   = kc;                // combine batch = warp id

    const float* WhL = Wh + (size_t)l * 768 * 256;

    // gates r,z rows for h=hout, k-chunk k0: packed k-pairs in regs
    ull w0r[32], w1r[32];
    {
        const ull* p0 = reinterpret_cast<const ull*>(
            WhL + ((size_t)(0 * 256 + hout)) * 256 + k0);
        const ull* p1 = reinterpret_cast<const ull*>(
            WhL + ((size_t)(1 * 256 + hout)) * 256 + k0);
#pragma unroll
        for (int q = 0; q < 32; q++) { w0r[q] = p0[q]; w1r[q] = p1[q]; }
    }
    // gate-n rows: sw3[kpair][lane] as float2 (pre-packed k-pairs)
    for (int i = tid; i < SW3_U; i += SC_THREADS) {
        int kp = i >> 5, ln = i & 31;
        const float* src = WhL + ((size_t)(2 * 256 + rank * 32 + ln)) * 256 + 2 * kp;
        reinterpret_cast<float2*>(sw3)[i] = make_float2(src[0], src[1]);
    }
    for (int i = tid; i < HBUF_F; i += SC_THREADS) hbuf[i] = 0.f;

    const float br = bh[l * 768 +       hout];
    const float bz = bh[l * 768 + 256 + hout];
    const float bn = bh[l * 768 + 512 + hout];

    // pre-map remote hbuf bases for all 8 ranks (loop-invariant)
    const uint32_t hbuf_saddr = (uint32_t)__cvta_generic_to_shared(hbuf);
    uint32_t rbase[8];
#pragma unroll
    for (int r8 = 0; r8 < 8; r8++)
        asm volatile("mapa.shared::cluster.u32 %0, %1, %2;"
                     : "=r"(rbase[r8]) : "r"(hbuf_saddr), "r"(r8));

    __syncthreads();
    cluster_arrive(); cluster_wait();   // init visible cluster-wide
    cluster_arrive();                   // pre-arm for iter-0 wait

    const size_t gsz = (size_t)BSZ * HID;
    float hprev = 0.f;
    int p = 0;

    for (int step = 0; step < T_LEN; step++) {
        const int t = dir ? (T_LEN - 1 - step) : step;

        // gx prefetch for this thread's (hout, batch bb) — hidden by the wait
        float gxr, gxz, gxn;
        {
            const size_t base = ((size_t)t * LAY + l) * 3 * gsz
                              + (size_t)(b0 + bb) * HID + hout;
            gxr = __ldg(g_gx + base);
            gxz = __ldg(g_gx + base + gsz);
            gxn = __ldg(g_gx + base + 2 * gsz);
        }

        cluster_wait();   // h(step-1) visible cluster-wide

        // --- dot: 3 gate-rows x 4 batches over 64 k, all packed k-pairs ---
        ull aR0 = 0, aR1 = 0, aR2 = 0, aR3 = 0;
        ull aZ0 = 0, aZ1 = 0, aZ2 = 0, aZ3 = 0;
        ull aN0 = 0, aN1 = 0, aN2 = 0, aN3 = 0;
        {
            const ulonglong2* h0p = reinterpret_cast<const ulonglong2*>(hbuf + ((p * 4 + 0) << 8) + k0);
            const ulonglong2* h1p = reinterpret_cast<const ulonglong2*>(hbuf + ((p * 4 + 1) << 8) + k0);
            const ulonglong2* h2p = reinterpret_cast<const ulonglong2*>(hbuf + ((p * 4 + 2) << 8) + k0);
            const ulonglong2* h3p = reinterpret_cast<const ulonglong2*>(hbuf + ((p * 4 + 3) << 8) + k0);
            const ull* w3p = sw3 + (k0 >> 1) * 32 + lane;   // stride 32 ull per kpair

#pragma unroll
            for (int q = 0; q < 16; q++) {
                const ull w3x = w3p[(2 * q) * 32];          // LDS.64, conflict-free,
                const ull w3y = w3p[(2 * q + 1) * 32];      // already k-pair packed
                const ulonglong2 hh0 = h0p[q];
                const ulonglong2 hh1 = h1p[q];
                const ulonglong2 hh2 = h2p[q];
                const ulonglong2 hh3 = h3p[q];
                const ull wa0 = w0r[2 * q], wa1 = w0r[2 * q + 1];
                const ull wb0 = w1r[2 * q], wb1 = w1r[2 * q + 1];
                ffma2(aR0, wa0, hh0.x); ffma2(aR0, wa1, hh0.y);
                ffma2(aR1, wa0, hh1.x); ffma2(aR1, wa1, hh1.y);
                ffma2(aR2, wa0, hh2.x); ffma2(aR2, wa1, hh2.y);
                ffma2(aR3, wa0, hh3.x); ffma2(aR3, wa1, hh3.y);
                ffma2(aZ0, wb0, hh0.x); ffma2(aZ0, wb1, hh0.y);
                ffma2(aZ1, wb0, hh1.x); ffma2(aZ1, wb1, hh1.y);
                ffma2(aZ2, wb0, hh2.x); ffma2(aZ2, wb1, hh2.y);
                ffma2(aZ3, wb0, hh3.x); ffma2(aZ3, wb1, hh3.y);
                ffma2(aN0, w3x, hh0.x); ffma2(aN0, w3y, hh0.y);
                ffma2(aN1, w3x, hh1.x); ffma2(aN1, w3y, hh1.y);
                ffma2(aN2, w3x, hh2.x); ffma2(aN2, w3y, hh2.y);
                ffma2(aN3, w3x, hh3.x); ffma2(aN3, w3y, hh3.y);
            }
        }
        // partial stores: part[b][kc][row], rows = gate*32+lane (conflict-free)
        {
            float* pb = part + kc * 96 + lane;
            pb[0 * 384 +  0] = hsum2(aR0); pb[0 * 384 + 32] = hsum2(aZ0); pb[0 * 384 + 64] = hsum2(aN0);
            pb[1 * 384 +  0] = hsum2(aR1); pb[1 * 384 + 32] = hsum2(aZ1); pb[1 * 384 + 64] = hsum2(aN1);
            pb[2 * 384 +  0] = hsum2(aR2); pb[2 * 384 + 32] = hsum2(aZ2); pb[2 * 384 + 64] = hsum2(aN2);
            pb[3 * 384 +  0] = hsum2(aR3); pb[3 * 384 + 32] = hsum2(aZ3); pb[3 * 384 + 64] = hsum2(aN3);
        }
        __syncthreads();

        // --- single-phase combine: thread owns (h=hout, batch bb) ---
        float h;
        {
            const float* pc = part + bb * 384 + lane;     // [kc][row] for batch bb
            const float sR = (pc[0 * 96] + pc[1 * 96]) + (pc[2 * 96] + pc[3 * 96]);
            const float sZ = (pc[0 * 96 + 32] + pc[1 * 96 + 32]) + (pc[2 * 96 + 32] + pc[3 * 96 + 32]);
            const float sN = (pc[0 * 96 + 64] + pc[1 * 96 + 64]) + (pc[2 * 96 + 64] + pc[3 * 96 + 64]);

            const float r = sig_fast(gxr + sR + br);
            const float z = sig_fast(gxz + sZ + bz);
            const float n = tanh_fast(gxn + r * (sN + bn));
            h = (1.f - z) * n + z * hprev;
            hprev = h;

            // broadcast h to all 8 ranks' hbuf[1-p][bb][hout]
            const uint32_t off = (uint32_t)(((((1 - p) * 4 + bb) << 8) + hout) * 4);
#pragma unroll
            for (int r8 = 0; r8 < 8; r8++)
                asm volatile("st.shared::cluster.f32 [%0], %1;"
                             :: "r"(rbase[r8] + off), "f"(h) : "memory");
        }

        cluster_arrive();   // release DSMEM stores; fences part/hbuf reuse

        out[(size_t)(b0 + bb) * ((size_t)T_LEN * LAY * 2 * HID)
            + ((size_t)t * LAY + l) * (2 * HID) + dir * HID + hout] = h;

        p ^= 1;
    }
    cluster_wait();
}

// ---------------------------------------------------------------------------
extern "C" void kernel_launch(void* const* d_in, const int* in_sizes, int n_in,
                              void* d_out, int out_size)
{
    (void)in_sizes; (void)n_in; (void)out_size;
    const float* x  = (const float*)d_in[0];
    const float* Wx = (const float*)d_in[1];
    const float* Wh = (const float*)d_in[2];
    const float* bx = (const float*)d_in[3];
    const float* bh = (const float*)d_in[4];
    float* out = (float*)d_out;

    const int smem1 = 4 * STG_F * 4;                                  // 139,264 B
    const int smem2 = (2 * SW3_U + PART_F + HBUF_F) * 4;              //  47,104 B

    cudaFuncSetAttribute(gx_gemm_kernel, cudaFuncAttributeMaxDynamicSharedMemorySize, smem1);
    cudaFuncSetAttribute(gru_scan_kernel, cudaFuncAttributeMaxDynamicSharedMemorySize, smem2);

    dim3 grid1(1536 / 128, 65536 / 128);   // 12 x 512 CTAs
    gx_gemm_kernel<<<grid1, 256, smem1>>>(x, Wx, bx);

    gru_scan_kernel<<<256, SC_THREADS, smem2>>>(Wh, bh, out);
}